// round 12
// baseline (speedup 1.0000x reference)
#include <cuda_runtime.h>
#include <cstdint>

#define BATCH 8
#define NANCH 25500
#define NCLS 80
#define PREDC 85
#define MAXDET 300
#define NBINS 1024
#define CMAX 1024
#define TOTDET (BATCH*MAXDET)   // 2400
#define FDIM 1920
#define HDIM 256
#define OUTC 260
#define MPAD 2432               // 38 * 64
#define NSLAB 4
#define KSLAB (FDIM/NSLAB)      // 480
#define NCHUNK (KSLAB/32)       // 15
#define NKT2 (HDIM/16)          // 16
#define SCOREBLKS 200
#define TRTILES 1536
#define W1TTILES 480            // (1920/32)*(256/32)
#define G1_SMEM 92160           // 2*(64*36 + 256*36)*4 bytes

typedef unsigned long long ull;

// ---------------- scratch (static device globals; no allocation) ----------------
__device__ __align__(16) float g_conf[BATCH*NANCH];
__device__ int   g_cls [BATCH*NANCH];
__device__ int   g_hist[BATCH*NBINS];
__device__ __align__(16) float g_boxes[TOTDET*4];
__device__ float g_keep [TOTDET];
__device__ __align__(16) float g_t1[BATCH*6400*128];
__device__ __align__(16) float g_t2[BATCH*1600*256];
__device__ __align__(16) float g_t3[BATCH*400*512];
__device__ __align__(16) float g_t4[BATCH*100*1024];
__device__ __align__(16) float g_F [(size_t)MPAD*FDIM];           // rows >=2400 stay zero
__device__ __align__(16) float g_W1t[(size_t)HDIM*FDIM];          // W1^T [n][k]
__device__ __align__(16) float g_part[(size_t)NSLAB*MPAD*HDIM];   // [slab][m][n]

// ---------------- asm helpers ----------------
__device__ __forceinline__ void cp16(void* s, const void* g) {
    unsigned ss = (unsigned)__cvta_generic_to_shared(s);
    asm volatile("cp.async.cg.shared.global [%0], [%1], 16;" :: "r"(ss), "l"(g));
}
#define CPCOMMIT asm volatile("cp.async.commit_group;" ::: "memory")
#define FFMA2(d,a,b) asm volatile("fma.rn.f32x2 %0, %1, %2, %0;" : "+l"(d) : "l"(a), "l"(b))
#define PACKDUP(d,x) asm volatile("mov.b64 %0, {%1, %1};" : "=l"(d) : "f"(x))
#define UNPACK2(lo,hi,v) asm volatile("mov.b64 {%0, %1}, %2;" : "=f"(lo), "=f"(hi) : "l"(v))
// m16n8k8 tf32 mma, D = A*B + D
#define MMA_TF32(c, a, b0, b1) asm volatile( \
    "mma.sync.aligned.m16n8k8.row.col.f32.tf32.tf32.f32 " \
    "{%0,%1,%2,%3}, {%4,%5,%6,%7}, {%8,%9}, {%0,%1,%2,%3};" \
    : "+f"((c)[0]), "+f"((c)[1]), "+f"((c)[2]), "+f"((c)[3]) \
    : "r"((a)[0]), "r"((a)[1]), "r"((a)[2]), "r"((a)[3]), "r"(b0), "r"(b1))

// ---------------- K1: fused score + feature transpose + W1 transpose ----------------
__global__ void __launch_bounds__(256) prep_kernel(const float* __restrict__ preds,
        const float* __restrict__ f1, const float* __restrict__ f2,
        const float* __restrict__ f3, const float* __restrict__ f4,
        const float* __restrict__ W1) {
    __shared__ __align__(16) char smraw[128*PREDC*4 + NBINS*4];
    int blk = blockIdx.x, b = blockIdx.y;
    int t = threadIdx.x;

    if (blk < SCOREBLKS) {
        float* s = (float*)smraw;
        int* shist = (int*)(smraw + 128*PREDC*4);
        int n0 = blk * 128;
        int cnt = NANCH - n0; if (cnt > 128) cnt = 128;
        for (int i = t; i < NBINS; i += 256) shist[i] = 0;
        const float4* src = (const float4*)(preds + ((size_t)b*NANCH + n0) * PREDC);
        float4* s4 = (float4*)s;
        int tot4 = cnt * PREDC / 4;
        for (int i = t; i < tot4; i += 256) s4[i] = src[i];
        __syncthreads();
        if (t < cnt) {
            const float* a = s + t*PREDC;
            float obj = a[4];
            float best = a[5]*obj; int bc = 0;
            #pragma unroll 8
            for (int c = 1; c < NCLS; c++) {
                float v = a[5+c]*obj;
                if (v > best) { best = v; bc = c; }
            }
            float conf = best > 0.1f ? best : 0.f;
            g_conf[(size_t)b*NANCH + n0 + t] = conf;
            g_cls [(size_t)b*NANCH + n0 + t] = bc;
            if (conf > 0.1f) {
                int bin = (int)((conf - 0.1f) * (1024.f/0.9f));
                bin = min(max(bin, 0), NBINS-1);
                atomicAdd(&shist[bin], 1);
            }
        }
        __syncthreads();
        for (int i = t; i < NBINS; i += 256) {
            int v = shist[i];
            if (v) atomicAdd(&g_hist[b*NBINS + i], v);
        }
    } else {
        float (*tile)[33] = (float(*)[33])smraw;
        int tl = blk - SCOREBLKS;
        const float* src; float* dst; int C, HW, tp;
        if (tl < 800)        {             src = f1; dst = g_t1;  C = 128;  HW = 6400; tp = 200; }
        else if (tl < 1200)  { tl -= 800;  src = f2; dst = g_t2;  C = 256;  HW = 1600; tp = 50; }
        else if (tl < 1408)  { tl -= 1200; src = f3; dst = g_t3;  C = 512;  HW = 400;  tp = 13; }
        else if (tl < 1536)  { tl -= 1408; src = f4; dst = g_t4;  C = 1024; HW = 100;  tp = 4; }
        else                 { if (b > 0) return;
                               tl -= 1536; src = W1; dst = g_W1t; C = 1920; HW = 256;  tp = 8; b = 0; }
        if (C != 1920) { src += (size_t)b*C*HW; dst += (size_t)b*C*HW; }
        int p0 = (tl % tp) * 32, c0 = (tl / tp) * 32;
        int tx = t & 7, ty = t >> 3;
        {
            int p = p0 + tx*4;
            if (p < HW) {
                float4 v = *(const float4*)(src + (size_t)(c0 + ty)*HW + p);
                tile[tx*4+0][ty] = v.x; tile[tx*4+1][ty] = v.y;
                tile[tx*4+2][ty] = v.z; tile[tx*4+3][ty] = v.w;
            }
        }
        __syncthreads();
        {
            int p = p0 + ty;
            if (p < HW) {
                float4 v = make_float4(tile[ty][tx*4+0], tile[ty][tx*4+1],
                                       tile[ty][tx*4+2], tile[ty][tx*4+3]);
                *(float4*)(dst + (size_t)p*C + c0 + tx*4) = v;
            }
        }
    }
}

// ---------------- K2: fused threshold + compact + rank + NMS ----------------
__global__ void __launch_bounds__(1024) select_kernel(const float* __restrict__ preds) {
    __shared__ int s[NBINS];
    __shared__ int sthr, scnt;
    __shared__ float cc[CMAX];
    __shared__ int   ci[CMAX];
    __shared__ float tv[MAXDET];
    __shared__ int   tti[MAXDET];
    __shared__ float sx1[MAXDET], sy1[MAXDET], sx2[MAXDET], sy2[MAXDET], sar[MAXDET];
    __shared__ int   scls[MAXDET];
    __shared__ unsigned supm[MAXDET][10];
    __shared__ unsigned keepw[10];
    int b = blockIdx.x, t = threadIdx.x;

    s[t] = g_hist[b*NBINS + t];
    g_hist[b*NBINS + t] = 0;
    __syncthreads();
    for (int off = 1; off < NBINS; off <<= 1) {
        int v = (t + off < NBINS) ? s[t + off] : 0;
        __syncthreads();
        s[t] += v;
        __syncthreads();
    }
    if (s[t] >= MAXDET && (t == NBINS-1 || s[t+1] < MAXDET)) sthr = t;
    if (t == 0) { if (s[0] < MAXDET) sthr = 0; scnt = 0; }
    __syncthreads();
    int thr = sthr;

    for (int i = t; i < NANCH; i += 1024) {
        float conf = g_conf[(size_t)b*NANCH + i];
        if (conf > 0.1f) {
            int bin = (int)((conf - 0.1f) * (1024.f/0.9f));
            bin = min(max(bin, 0), NBINS-1);
            if (bin >= thr) {
                int p = atomicAdd(&scnt, 1);
                if (p < CMAX) { cc[p] = conf; ci[p] = i; }
            }
        }
    }
    __syncthreads();
    int M = min(scnt, CMAX);

    if (t < MAXDET) { tv[t] = 0.f; tti[t] = 0; }
    __syncthreads();
    for (int i = t; i < M; i += 1024) {
        float c = cc[i]; int id = ci[i];
        int r = 0;
        for (int j = 0; j < M; j++) {
            float cj = cc[j];
            r += (cj > c) || (cj == c && ci[j] < id);
        }
        if (r < MAXDET) { tv[r] = c; tti[r] = id; }
    }
    __syncthreads();

    bool act = t < MAXDET;
    bool valid = false;
    if (act) {
        int idx = tti[t];
        float conf = tv[t];
        const float* p = preds + ((size_t)b*NANCH + idx) * PREDC;
        float xc = p[0], yc = p[1], w = p[2], h = p[3];
        float x1 = xc - w*0.5f, y1 = yc - h*0.5f;
        float x2 = xc + w*0.5f, y2 = yc + h*0.5f;
        float* gb = g_boxes + ((size_t)b*MAXDET + t)*4;
        gb[0]=x1; gb[1]=y1; gb[2]=x2; gb[3]=y2;
        int cls = g_cls[(size_t)b*NANCH + idx];
        float off = (float)cls * 4096.0f;
        float vx1 = x1+off, vy1 = y1+off, vx2 = x2+off, vy2 = y2+off;
        sx1[t]=vx1; sy1[t]=vy1; sx2[t]=vx2; sy2[t]=vy2;
        sar[t] = (vx2-vx1)*(vy2-vy1);
        scls[t] = cls;
        valid = conf > 0.1f;
    }
    if (t < 320) {
        unsigned vb = __ballot_sync(0xffffffffu, valid);
        if ((t & 31) == 0) keepw[t >> 5] = vb;
    }
    __syncthreads();

    {
        int warp = t >> 5, lane = t & 31;
        for (int job = warp; job < MAXDET*10; job += 32) {
            int i = job / 10, word = job - i*10;
            int jb = word*32 + lane;
            int ic = scls[i];
            bool lact = (jb < MAXDET) && (jb > i);
            bool cm = lact && (scls[jb] == ic);
            unsigned anym = __ballot_sync(0xffffffffu, cm);
            bool sup = false;
            if (anym) {
                float ix1 = sx1[i], iy1 = sy1[i], ix2 = sx2[i], iy2 = sy2[i], iar = sar[i];
                if (cm) {
                    float lx = fmaxf(ix1, sx1[jb]), lyv = fmaxf(iy1, sy1[jb]);
                    float rx = fminf(ix2, sx2[jb]), ry  = fminf(iy2, sy2[jb]);
                    float iw = fmaxf(rx - lx, 0.f), ih = fmaxf(ry - lyv, 0.f);
                    float inter = iw * ih;
                    float iou = inter / (iar + sar[jb] - inter + 1e-7f);
                    sup = iou > 0.6f;
                }
            }
            unsigned m = __ballot_sync(0xffffffffu, sup);
            if (lane == 0) supm[i][word] = m;
        }
    }
    __syncthreads();

    if (t == 0) {
        unsigned kw[10];
        #pragma unroll
        for (int w = 0; w < 10; w++) kw[w] = keepw[w];
        #pragma unroll
        for (int w = 0; w < 10; w++) {
            unsigned bits = kw[w];
            while (bits) {
                int bit = __ffs(bits) - 1;
                bits &= bits - 1;
                int i = w*32 + bit;
                #pragma unroll
                for (int w2 = 0; w2 < 10; w2++) kw[w2] &= ~supm[i][w2];
                bits &= kw[w];
            }
        }
        #pragma unroll
        for (int w = 0; w < 10; w++) keepw[w] = kw[w];
    }
    __syncthreads();
    if (act) g_keep[b*MAXDET + t] = ((keepw[t>>5] >> (t&31)) & 1u) ? 1.f : 0.f;
}

// ---------------- K3: ROI align 1x1 ----------------
__global__ void __launch_bounds__(480) roi_kernel() {
    int det = blockIdx.x, b = blockIdx.y;
    int row = b*MAXDET + det;
    const float* gb = g_boxes + (size_t)row*4;
    float bx1 = gb[0], by1 = gb[1], bx2 = gb[2], by2 = gb[3];
    int q = threadIdx.x;
    const float* T; int C, H, W; float scale; int c0;
    if (q < 32)       { T = g_t1 + (size_t)b*6400*128; C = 128;  H = 80; W = 80; scale = 0.125f;    c0 = q*4; }
    else if (q < 96)  { T = g_t2 + (size_t)b*1600*256; C = 256;  H = 40; W = 40; scale = 0.0625f;   c0 = (q-32)*4; }
    else if (q < 224) { T = g_t3 + (size_t)b*400*512;  C = 512;  H = 20; W = 20; scale = 0.03125f;  c0 = (q-96)*4; }
    else              { T = g_t4 + (size_t)b*100*1024; C = 1024; H = 10; W = 10; scale = 0.015625f; c0 = (q-224)*4; }

    float x1 = bx1*scale, y1 = by1*scale, x2 = bx2*scale, y2 = by2*scale;
    float w = fmaxf(x2-x1, 1.f), h = fmaxf(y2-y1, 1.f);
    float xs[2] = { x1 + 0.5f*(w*0.5f), x1 + 1.5f*(w*0.5f) };
    float ys[2] = { y1 + 0.5f*(h*0.5f), y1 + 1.5f*(h*0.5f) };
    int pos[16]; float wt[16];
    int k = 0;
    #pragma unroll
    for (int py = 0; py < 2; py++) {
        #pragma unroll
        for (int px = 0; px < 2; px++) {
            float y = fminf(fmaxf(ys[py], 0.f), (float)(H-1));
            float x = fminf(fmaxf(xs[px], 0.f), (float)(W-1));
            float y0f = floorf(y), x0f = floorf(x);
            int y0 = (int)y0f, x0 = (int)x0f;
            int y1i = min(y0+1, H-1), x1i = min(x0+1, W-1);
            float ly = y - y0f, lx = x - x0f;
            pos[k] = (y0 *W + x0 )*C; wt[k] = (1.f-ly)*(1.f-lx)*0.25f; k++;
            pos[k] = (y0 *W + x1i)*C; wt[k] = (1.f-ly)*lx*0.25f;       k++;
            pos[k] = (y1i*W + x0 )*C; wt[k] = ly*(1.f-lx)*0.25f;       k++;
            pos[k] = (y1i*W + x1i)*C; wt[k] = ly*lx*0.25f;             k++;
        }
    }
    float4 acc = make_float4(0.f, 0.f, 0.f, 0.f);
    #pragma unroll
    for (int i = 0; i < 16; i++) {
        float4 v = *(const float4*)(T + pos[i] + c0);
        float wv = wt[i];
        acc.x += wv*v.x; acc.y += wv*v.y; acc.z += wv*v.z; acc.w += wv*v.w;
    }
    *(float4*)(g_F + (size_t)row*FDIM + q*4) = acc;
}

// ---------------- K4: GEMM1 via mma.sync tf32 (152 blocks, tile 64x256, split-K 4) ----------------
__global__ void __launch_bounds__(256) gemm1_mma() {
    extern __shared__ __align__(16) float dsm[];
    // layout (floats): As0[2304] As1[2304] Bs0[9216] Bs1[9216]  (ld = 36)
    float* const AsP[2] = { dsm, dsm + 2304 };
    float* const BsP[2] = { dsm + 4608, dsm + 4608 + 9216 };
    int tid = threadIdx.x;
    int m0 = blockIdx.x * 64;
    int slab = blockIdx.y;
    int kb = slab * KSLAB;
    int wid = tid >> 5, lane = tid & 31;
    int wm = wid >> 2, wn = wid & 3;        // warps: 2 (m) x 4 (n)
    int gid = lane >> 2, tg = lane & 3;

    const float* aBase = g_F + (size_t)m0*FDIM + kb;
    const float* bBase = g_W1t + kb;
    int ar = tid >> 2, aq2 = (tid & 3) * 2;   // A loader: row ar, chunks aq2, aq2+1

    #define G1_LOAD(c, s) do { \
        int _c32 = (c)*32; \
        float* _A = AsP[s]; float* _B = BsP[s]; \
        cp16(_A + ar*36 + aq2*4,     aBase + (size_t)ar*FDIM + _c32 + aq2*4); \
        cp16(_A + ar*36 + aq2*4 + 4, aBase + (size_t)ar*FDIM + _c32 + aq2*4 + 4); \
        _Pragma("unroll") \
        for (int j = 0; j < 8; j++) \
            cp16(_B + tid*36 + j*4, bBase + (size_t)tid*FDIM + _c32 + j*4); \
        CPCOMMIT; \
    } while (0)

    G1_LOAD(0, 0);

    float c[2][8][4];
    #pragma unroll
    for (int mt = 0; mt < 2; mt++)
        #pragma unroll
        for (int nt = 0; nt < 8; nt++)
            #pragma unroll
            for (int j = 0; j < 4; j++) c[mt][nt][j] = 0.f;

    #pragma unroll 1
    for (int ch = 0; ch < NCHUNK; ch++) {
        int s = ch & 1;
        if (ch + 1 < NCHUNK) {
            G1_LOAD(ch+1, s^1);
            asm volatile("cp.async.wait_group 1;" ::: "memory");
        } else {
            asm volatile("cp.async.wait_group 0;" ::: "memory");
        }
        __syncthreads();
        const float* Asp = AsP[s];
        const float* Bsp = BsP[s];
        #pragma unroll
        for (int k8 = 0; k8 < 4; k8++) {
            int kc = k8*8 + tg;
            uint32_t a[2][4];
            #pragma unroll
            for (int mt = 0; mt < 2; mt++) {
                const float* ap = Asp + (wm*32 + mt*16 + gid)*36 + kc;
                a[mt][0] = __float_as_uint(ap[0]);
                a[mt][1] = __float_as_uint(ap[8*36]);
                a[mt][2] = __float_as_uint(ap[4]);
                a[mt][3] = __float_as_uint(ap[8*36 + 4]);
            }
            #pragma unroll
            for (int nt = 0; nt < 8; nt++) {
                const float* bp = Bsp + (wn*64 + nt*8 + gid)*36 + kc;
                uint32_t b0 = __float_as_uint(bp[0]);
                uint32_t b1 = __float_as_uint(bp[4]);
                MMA_TF32(c[0][nt], a[0], b0, b1);
                MMA_TF32(c[1][nt], a[1], b0, b1);
            }
        }
        __syncthreads();
    }

    // epilogue: fragments -> g_part[slab][m][n]
    #pragma unroll
    for (int mt = 0; mt < 2; mt++) {
        int m = m0 + wm*32 + mt*16 + gid;
        float* rp = g_part + ((size_t)slab*MPAD + m)*HDIM + wn*64 + tg*2;
        #pragma unroll
        for (int nt = 0; nt < 8; nt++) {
            *(float2*)(rp + nt*8)            = make_float2(c[mt][nt][0], c[mt][nt][1]);
            *(float2*)(rp + nt*8 + 8*HDIM)   = make_float2(c[mt][nt][2], c[mt][nt][3]);
        }
    }
}

// ---------------- K5: GEMM2 + slab reduce + bias/leaky + keep + bb ----------------
__global__ void __launch_bounds__(256) gemm2_kernel(const float* __restrict__ W2,
        const float* __restrict__ b1, const float* __restrict__ b2,
        const float* __restrict__ orig_hw, float* __restrict__ out) {
    __shared__ __align__(16) float Ah[HDIM][16];     // [k][m]
    __shared__ __align__(16) float Bs[2][16][256];
    int m0 = blockIdx.x * 16;
    int tid = threadIdx.x;

    // A panel: reduce NSLAB slabs + b1 + leaky, store transposed
    #pragma unroll
    for (int q = 0; q < 4; q++) {
        int pos = q*256 + tid;
        int r = pos >> 6, f = pos & 63;
        const float* p0 = g_part + ((size_t)(m0 + r))*HDIM + f*4;
        float4 bv = *(const float4*)(b1 + f*4);
        float v0 = bv.x, v1 = bv.y, v2 = bv.z, v3 = bv.w;
        #pragma unroll
        for (int sl = 0; sl < NSLAB; sl++) {
            float4 sv = *(const float4*)(p0 + (size_t)sl*MPAD*HDIM);
            v0 += sv.x; v1 += sv.y; v2 += sv.z; v3 += sv.w;
        }
        v0 = v0 > 0.f ? v0 : 0.01f*v0;
        v1 = v1 > 0.f ? v1 : 0.01f*v1;
        v2 = v2 > 0.f ? v2 : 0.01f*v2;
        v3 = v3 > 0.f ? v3 : 0.01f*v3;
        Ah[f*4+0][r] = v0; Ah[f*4+1][r] = v1; Ah[f*4+2][r] = v2; Ah[f*4+3][r] = v3;
    }

    {
        int br = tid >> 6, bf = tid & 63;
        #pragma unroll
        for (int i = 0; i < 4; i++)
            cp16(&Bs[0][br + i*4][bf*4], W2 + (size_t)(br + i*4)*256 + bf*4);
        CPCOMMIT;
    }
    __syncthreads();

    int ty = tid >> 6, tx = tid & 63;
    ull acc[2][4];
    #pragma unroll
    for (int h = 0; h < 2; h++)
        #pragma unroll
        for (int j = 0; j < 4; j++) acc[h][j] = 0ull;

    #pragma unroll 1
    for (int kt = 0; kt < NKT2; kt++) {
        int st = kt & 1;
        if (kt + 1 < NKT2) {
            int br = tid >> 6, bf = tid & 63;
            #pragma unroll
            for (int i = 0; i < 4; i++)
                cp16(&Bs[st^1][br + i*4][bf*4], W2 + (size_t)((kt+1)*16 + br + i*4)*256 + bf*4);
            CPCOMMIT;
            asm volatile("cp.async.wait_group 1;" ::: "memory");
        } else {
            asm volatile("cp.async.wait_group 0;" ::: "memory");
        }
        __syncthreads();
        #pragma unroll
        for (int k = 0; k < 16; k++) {
            int kk = kt*16 + k;
            ull a0 = *(const ull*)&Ah[kk][ty*4];
            ull a1 = *(const ull*)&Ah[kk][ty*4 + 2];
            float4 bq = *(const float4*)&Bs[st][k][tx*4];
            ull bd[4];
            PACKDUP(bd[0], bq.x); PACKDUP(bd[1], bq.y); PACKDUP(bd[2], bq.z); PACKDUP(bd[3], bq.w);
            #pragma unroll
            for (int j = 0; j < 4; j++) { FFMA2(acc[0][j], a0, bd[j]); FFMA2(acc[1][j], a1, bd[j]); }
        }
        __syncthreads();
    }

    float4 bv2 = *(const float4*)(b2 + tx*4);
    float bb2[4] = { bv2.x, bv2.y, bv2.z, bv2.w };
    #pragma unroll
    for (int h = 0; h < 2; h++) {
        float lo[4], hi[4];
        #pragma unroll
        for (int j = 0; j < 4; j++) UNPACK2(lo[j], hi[j], acc[h][j]);
        int mr = m0 + ty*4 + 2*h;
        float kf0 = g_keep[mr], kf1 = g_keep[mr+1];
        float o0[4], o1[4];
        #pragma unroll
        for (int j = 0; j < 4; j++) {
            float v = lo[j] + bb2[j]; v = v > 0.f ? v : 0.01f*v; o0[j] = v * kf0;
            float u = hi[j] + bb2[j]; u = u > 0.f ? u : 0.01f*u; o1[j] = u * kf1;
        }
        *(float4*)(out + (size_t)mr*OUTC + 4 + tx*4)     = make_float4(o0[0],o0[1],o0[2],o0[3]);
        *(float4*)(out + (size_t)(mr+1)*OUTC + 4 + tx*4) = make_float4(o1[0],o1[1],o1[2],o1[3]);
    }

    if (tid < 16) {
        int m = m0 + tid;
        int bidx = m / MAXDET;
        const float* gb = g_boxes + (size_t)m*4;
        float oh = orig_hw[bidx*2 + 0], ow = orig_hw[bidx*2 + 1];
        float gain = fminf(640.f/oh, 640.f/ow);
        float padx = (640.f - ow*gain) * 0.5f;
        float pady = (640.f - oh*gain) * 0.5f;
        float kf = g_keep[m];
        float x1 = fminf(fmaxf((gb[0]-padx)/gain, 0.f), ow);
        float y1 = fminf(fmaxf((gb[1]-pady)/gain, 0.f), oh);
        float x2 = fminf(fmaxf((gb[2]-padx)/gain, 0.f), ow);
        float y2 = fminf(fmaxf((gb[3]-pady)/gain, 0.f), oh);
        *(float4*)(out + (size_t)m*OUTC) = make_float4(x1/ow*kf, y1/oh*kf, x2/ow*kf, y2/oh*kf);
    }
}

// ---------------- launch ----------------
extern "C" void kernel_launch(void* const* d_in, const int* in_sizes, int n_in,
                              void* d_out, int out_size) {
    const float* preds   = (const float*)d_in[0];
    const float* feat1   = (const float*)d_in[1];
    const float* feat2   = (const float*)d_in[2];
    const float* feat3   = (const float*)d_in[3];
    const float* feat4   = (const float*)d_in[4];
    const float* orig_hw = (const float*)d_in[5];
    const float* W1      = (const float*)d_in[6];
    const float* b1      = (const float*)d_in[7];
    const float* W2      = (const float*)d_in[8];
    const float* b2      = (const float*)d_in[9];
    float* out = (float*)d_out;
    (void)in_sizes; (void)n_in; (void)out_size;

    cudaFuncSetAttribute(gemm1_mma, cudaFuncAttributeMaxDynamicSharedMemorySize, G1_SMEM);

    prep_kernel<<<dim3(SCOREBLKS + TRTILES + W1TTILES, BATCH), 256>>>(preds, feat1, feat2, feat3, feat4, W1);
    select_kernel<<<BATCH, 1024>>>(preds);
    roi_kernel<<<dim3(MAXDET, BATCH), 480>>>();
    gemm1_mma<<<dim3(MPAD/64, NSLAB), 256, G1_SMEM>>>();
    gemm2_kernel<<<TOTDET/16, 256>>>(W2, b1, b2, orig_hw, out);
}

// round 14
// speedup vs baseline: 1.0869x; 1.0869x over previous
#include <cuda_runtime.h>
#include <cstdint>

#define BATCH 8
#define NANCH 25500
#define NCLS 80
#define PREDC 85
#define MAXDET 300
#define NBINS 1024
#define CMAX 1024
#define TOTDET (BATCH*MAXDET)   // 2400
#define FDIM 1920
#define HDIM 256
#define OUTC 260
#define MPAD 2432               // 38 * 64
#define NSLAB 3
#define KSLAB (FDIM/NSLAB)      // 640
#define NCHUNK (KSLAB/32)       // 20
#define NKT2 (HDIM/16)          // 16
#define SCOREBLKS 200
#define TRTILES 1536
#define W1TTILES 480            // (1920/32)*(256/32)
#define G1_STAGE 11520          // (64*36 + 256*36) floats
#define G1_SMEM (3*G1_STAGE*4)  // 138240 B

typedef unsigned long long ull;

// ---------------- scratch (static device globals; no allocation) ----------------
__device__ __align__(16) float g_conf[BATCH*NANCH];
__device__ int   g_cls [BATCH*NANCH];
__device__ int   g_hist[BATCH*NBINS];
__device__ __align__(16) float g_boxes[TOTDET*4];
__device__ float g_keep [TOTDET];
__device__ __align__(16) float g_t1[BATCH*6400*128];
__device__ __align__(16) float g_t2[BATCH*1600*256];
__device__ __align__(16) float g_t3[BATCH*400*512];
__device__ __align__(16) float g_t4[BATCH*100*1024];
__device__ __align__(16) float g_F [(size_t)MPAD*FDIM];           // rows >=2400 stay zero
__device__ __align__(16) float g_W1t[(size_t)HDIM*FDIM];          // W1^T [n][k]
__device__ __align__(16) float g_part[(size_t)NSLAB*MPAD*HDIM];   // [slab][m][n]

// ---------------- asm helpers ----------------
__device__ __forceinline__ void cp16(void* s, const void* g) {
    unsigned ss = (unsigned)__cvta_generic_to_shared(s);
    asm volatile("cp.async.cg.shared.global [%0], [%1], 16;" :: "r"(ss), "l"(g));
}
#define CPCOMMIT asm volatile("cp.async.commit_group;" ::: "memory")
#define CPWAIT(n) asm volatile("cp.async.wait_group %0;" :: "n"(n) : "memory")
#define FFMA2(d,a,b) asm volatile("fma.rn.f32x2 %0, %1, %2, %0;" : "+l"(d) : "l"(a), "l"(b))
#define PACKDUP(d,x) asm volatile("mov.b64 %0, {%1, %1};" : "=l"(d) : "f"(x))
#define UNPACK2(lo,hi,v) asm volatile("mov.b64 {%0, %1}, %2;" : "=f"(lo), "=f"(hi) : "l"(v))
// m16n8k8 tf32 mma, D = A*B + D
#define MMA_TF32(c, a, b0, b1) asm volatile( \
    "mma.sync.aligned.m16n8k8.row.col.f32.tf32.tf32.f32 " \
    "{%0,%1,%2,%3}, {%4,%5,%6,%7}, {%8,%9}, {%0,%1,%2,%3};" \
    : "+f"((c)[0]), "+f"((c)[1]), "+f"((c)[2]), "+f"((c)[3]) \
    : "r"((a)[0]), "r"((a)[1]), "r"((a)[2]), "r"((a)[3]), "r"(b0), "r"(b1))

// ---------------- K1: fused score + feature transpose + W1 transpose ----------------
__global__ void __launch_bounds__(256) prep_kernel(const float* __restrict__ preds,
        const float* __restrict__ f1, const float* __restrict__ f2,
        const float* __restrict__ f3, const float* __restrict__ f4,
        const float* __restrict__ W1) {
    __shared__ __align__(16) char smraw[128*PREDC*4 + NBINS*4];
    int blk = blockIdx.x, b = blockIdx.y;
    int t = threadIdx.x;

    if (blk < SCOREBLKS) {
        float* s = (float*)smraw;
        int* shist = (int*)(smraw + 128*PREDC*4);
        int n0 = blk * 128;
        int cnt = NANCH - n0; if (cnt > 128) cnt = 128;
        for (int i = t; i < NBINS; i += 256) shist[i] = 0;
        const float4* src = (const float4*)(preds + ((size_t)b*NANCH + n0) * PREDC);
        float4* s4 = (float4*)s;
        int tot4 = cnt * PREDC / 4;
        for (int i = t; i < tot4; i += 256) s4[i] = src[i];
        __syncthreads();
        if (t < cnt) {
            const float* a = s + t*PREDC;
            float obj = a[4];
            float best = a[5]*obj; int bc = 0;
            #pragma unroll 8
            for (int c = 1; c < NCLS; c++) {
                float v = a[5+c]*obj;
                if (v > best) { best = v; bc = c; }
            }
            float conf = best > 0.1f ? best : 0.f;
            g_conf[(size_t)b*NANCH + n0 + t] = conf;
            g_cls [(size_t)b*NANCH + n0 + t] = bc;
            if (conf > 0.1f) {
                int bin = (int)((conf - 0.1f) * (1024.f/0.9f));
                bin = min(max(bin, 0), NBINS-1);
                atomicAdd(&shist[bin], 1);
            }
        }
        __syncthreads();
        for (int i = t; i < NBINS; i += 256) {
            int v = shist[i];
            if (v) atomicAdd(&g_hist[b*NBINS + i], v);
        }
    } else {
        float (*tile)[33] = (float(*)[33])smraw;
        int tl = blk - SCOREBLKS;
        const float* src; float* dst; int C, HW, tp;
        if (tl < 800)        {             src = f1; dst = g_t1;  C = 128;  HW = 6400; tp = 200; }
        else if (tl < 1200)  { tl -= 800;  src = f2; dst = g_t2;  C = 256;  HW = 1600; tp = 50; }
        else if (tl < 1408)  { tl -= 1200; src = f3; dst = g_t3;  C = 512;  HW = 400;  tp = 13; }
        else if (tl < 1536)  { tl -= 1408; src = f4; dst = g_t4;  C = 1024; HW = 100;  tp = 4; }
        else                 { if (b > 0) return;
                               tl -= 1536; src = W1; dst = g_W1t; C = 1920; HW = 256;  tp = 8; b = 0; }
        if (C != 1920) { src += (size_t)b*C*HW; dst += (size_t)b*C*HW; }
        int p0 = (tl % tp) * 32, c0 = (tl / tp) * 32;
        int tx = t & 7, ty = t >> 3;
        {
            int p = p0 + tx*4;
            if (p < HW) {
                float4 v = *(const float4*)(src + (size_t)(c0 + ty)*HW + p);
                tile[tx*4+0][ty] = v.x; tile[tx*4+1][ty] = v.y;
                tile[tx*4+2][ty] = v.z; tile[tx*4+3][ty] = v.w;
            }
        }
        __syncthreads();
        {
            int p = p0 + ty;
            if (p < HW) {
                float4 v = make_float4(tile[ty][tx*4+0], tile[ty][tx*4+1],
                                       tile[ty][tx*4+2], tile[ty][tx*4+3]);
                *(float4*)(dst + (size_t)p*C + c0 + tx*4) = v;
            }
        }
    }
}

// ---------------- K2: fused threshold + compact + rank + NMS ----------------
__global__ void __launch_bounds__(1024) select_kernel(const float* __restrict__ preds) {
    __shared__ int s[NBINS];
    __shared__ int sthr, scnt;
    __shared__ float cc[CMAX];
    __shared__ int   ci[CMAX];
    __shared__ float tv[MAXDET];
    __shared__ int   tti[MAXDET];
    __shared__ float sx1[MAXDET], sy1[MAXDET], sx2[MAXDET], sy2[MAXDET], sar[MAXDET];
    __shared__ int   scls[MAXDET];
    __shared__ unsigned supm[MAXDET][10];
    __shared__ unsigned keepw[10];
    int b = blockIdx.x, t = threadIdx.x;

    s[t] = g_hist[b*NBINS + t];
    g_hist[b*NBINS + t] = 0;
    __syncthreads();
    for (int off = 1; off < NBINS; off <<= 1) {
        int v = (t + off < NBINS) ? s[t + off] : 0;
        __syncthreads();
        s[t] += v;
        __syncthreads();
    }
    if (s[t] >= MAXDET && (t == NBINS-1 || s[t+1] < MAXDET)) sthr = t;
    if (t == 0) { if (s[0] < MAXDET) sthr = 0; scnt = 0; }
    __syncthreads();
    int thr = sthr;

    for (int i = t; i < NANCH; i += 1024) {
        float conf = g_conf[(size_t)b*NANCH + i];
        if (conf > 0.1f) {
            int bin = (int)((conf - 0.1f) * (1024.f/0.9f));
            bin = min(max(bin, 0), NBINS-1);
            if (bin >= thr) {
                int p = atomicAdd(&scnt, 1);
                if (p < CMAX) { cc[p] = conf; ci[p] = i; }
            }
        }
    }
    __syncthreads();
    int M = min(scnt, CMAX);

    if (t < MAXDET) { tv[t] = 0.f; tti[t] = 0; }
    __syncthreads();
    for (int i = t; i < M; i += 1024) {
        float c = cc[i]; int id = ci[i];
        int r = 0;
        for (int j = 0; j < M; j++) {
            float cj = cc[j];
            r += (cj > c) || (cj == c && ci[j] < id);
        }
        if (r < MAXDET) { tv[r] = c; tti[r] = id; }
    }
    __syncthreads();

    bool act = t < MAXDET;
    bool valid = false;
    if (act) {
        int idx = tti[t];
        float conf = tv[t];
        const float* p = preds + ((size_t)b*NANCH + idx) * PREDC;
        float xc = p[0], yc = p[1], w = p[2], h = p[3];
        float x1 = xc - w*0.5f, y1 = yc - h*0.5f;
        float x2 = xc + w*0.5f, y2 = yc + h*0.5f;
        float* gb = g_boxes + ((size_t)b*MAXDET + t)*4;
        gb[0]=x1; gb[1]=y1; gb[2]=x2; gb[3]=y2;
        int cls = g_cls[(size_t)b*NANCH + idx];
        float off = (float)cls * 4096.0f;
        float vx1 = x1+off, vy1 = y1+off, vx2 = x2+off, vy2 = y2+off;
        sx1[t]=vx1; sy1[t]=vy1; sx2[t]=vx2; sy2[t]=vy2;
        sar[t] = (vx2-vx1)*(vy2-vy1);
        scls[t] = cls;
        valid = conf > 0.1f;
    }
    if (t < 320) {
        unsigned vb = __ballot_sync(0xffffffffu, valid);
        if ((t & 31) == 0) keepw[t >> 5] = vb;
    }
    __syncthreads();

    {
        int warp = t >> 5, lane = t & 31;
        for (int job = warp; job < MAXDET*10; job += 32) {
            int i = job / 10, word = job - i*10;
            int jb = word*32 + lane;
            int ic = scls[i];
            bool lact = (jb < MAXDET) && (jb > i);
            bool cm = lact && (scls[jb] == ic);
            unsigned anym = __ballot_sync(0xffffffffu, cm);
            bool sup = false;
            if (anym) {
                float ix1 = sx1[i], iy1 = sy1[i], ix2 = sx2[i], iy2 = sy2[i], iar = sar[i];
                if (cm) {
                    float lx = fmaxf(ix1, sx1[jb]), lyv = fmaxf(iy1, sy1[jb]);
                    float rx = fminf(ix2, sx2[jb]), ry  = fminf(iy2, sy2[jb]);
                    float iw = fmaxf(rx - lx, 0.f), ih = fmaxf(ry - lyv, 0.f);
                    float inter = iw * ih;
                    float iou = inter / (iar + sar[jb] - inter + 1e-7f);
                    sup = iou > 0.6f;
                }
            }
            unsigned m = __ballot_sync(0xffffffffu, sup);
            if (lane == 0) supm[i][word] = m;
        }
    }
    __syncthreads();

    if (t == 0) {
        unsigned kw[10];
        #pragma unroll
        for (int w = 0; w < 10; w++) kw[w] = keepw[w];
        #pragma unroll
        for (int w = 0; w < 10; w++) {
            unsigned bits = kw[w];
            while (bits) {
                int bit = __ffs(bits) - 1;
                bits &= bits - 1;
                int i = w*32 + bit;
                #pragma unroll
                for (int w2 = 0; w2 < 10; w2++) kw[w2] &= ~supm[i][w2];
                bits &= kw[w];
            }
        }
        #pragma unroll
        for (int w = 0; w < 10; w++) keepw[w] = kw[w];
    }
    __syncthreads();
    if (act) g_keep[b*MAXDET + t] = ((keepw[t>>5] >> (t&31)) & 1u) ? 1.f : 0.f;
}

// ---------------- K3: ROI align 1x1 ----------------
__global__ void __launch_bounds__(480) roi_kernel() {
    int det = blockIdx.x, b = blockIdx.y;
    int row = b*MAXDET + det;
    const float* gb = g_boxes + (size_t)row*4;
    float bx1 = gb[0], by1 = gb[1], bx2 = gb[2], by2 = gb[3];
    int q = threadIdx.x;
    const float* T; int C, H, W; float scale; int c0;
    if (q < 32)       { T = g_t1 + (size_t)b*6400*128; C = 128;  H = 80; W = 80; scale = 0.125f;    c0 = q*4; }
    else if (q < 96)  { T = g_t2 + (size_t)b*1600*256; C = 256;  H = 40; W = 40; scale = 0.0625f;   c0 = (q-32)*4; }
    else if (q < 224) { T = g_t3 + (size_t)b*400*512;  C = 512;  H = 20; W = 20; scale = 0.03125f;  c0 = (q-96)*4; }
    else              { T = g_t4 + (size_t)b*100*1024; C = 1024; H = 10; W = 10; scale = 0.015625f; c0 = (q-224)*4; }

    float x1 = bx1*scale, y1 = by1*scale, x2 = bx2*scale, y2 = by2*scale;
    float w = fmaxf(x2-x1, 1.f), h = fmaxf(y2-y1, 1.f);
    float xs[2] = { x1 + 0.5f*(w*0.5f), x1 + 1.5f*(w*0.5f) };
    float ys[2] = { y1 + 0.5f*(h*0.5f), y1 + 1.5f*(h*0.5f) };
    int pos[16]; float wt[16];
    int k = 0;
    #pragma unroll
    for (int py = 0; py < 2; py++) {
        #pragma unroll
        for (int px = 0; px < 2; px++) {
            float y = fminf(fmaxf(ys[py], 0.f), (float)(H-1));
            float x = fminf(fmaxf(xs[px], 0.f), (float)(W-1));
            float y0f = floorf(y), x0f = floorf(x);
            int y0 = (int)y0f, x0 = (int)x0f;
            int y1i = min(y0+1, H-1), x1i = min(x0+1, W-1);
            float ly = y - y0f, lx = x - x0f;
            pos[k] = (y0 *W + x0 )*C; wt[k] = (1.f-ly)*(1.f-lx)*0.25f; k++;
            pos[k] = (y0 *W + x1i)*C; wt[k] = (1.f-ly)*lx*0.25f;       k++;
            pos[k] = (y1i*W + x0 )*C; wt[k] = ly*(1.f-lx)*0.25f;       k++;
            pos[k] = (y1i*W + x1i)*C; wt[k] = ly*lx*0.25f;             k++;
        }
    }
    float4 acc = make_float4(0.f, 0.f, 0.f, 0.f);
    #pragma unroll
    for (int i = 0; i < 16; i++) {
        float4 v = *(const float4*)(T + pos[i] + c0);
        float wv = wt[i];
        acc.x += wv*v.x; acc.y += wv*v.y; acc.z += wv*v.z; acc.w += wv*v.w;
    }
    *(float4*)(g_F + (size_t)row*FDIM + q*4) = acc;
}

// ---------------- K4: GEMM1 via mma.sync tf32 (114 blocks, single wave, 3-stage pipeline) ----------------
__global__ void __launch_bounds__(256) gemm1_mma() {
    extern __shared__ __align__(16) float dsm[];
    // stage layout (floats): A[64*36] then B[256*36], 3 stages
    int tid = threadIdx.x;
    int m0 = blockIdx.x * 64;
    int slab = blockIdx.y;
    int kb = slab * KSLAB;
    int wid = tid >> 5, lane = tid & 31;
    int wm = wid >> 2, wn = wid & 3;        // warps: 2 (m) x 4 (n)
    int gid = lane >> 2, tg = lane & 3;

    const float* aBase = g_F + (size_t)m0*FDIM + kb;
    const float* bBase = g_W1t + kb;
    int ar = tid >> 2, aq2 = (tid & 3) * 2;   // A loader: row ar, float4 chunks aq2, aq2+1

    #define G1_LOAD(c, s) do { \
        int _c32 = (c)*32; \
        float* _A = dsm + (s)*G1_STAGE; float* _B = _A + 64*36; \
        cp16(_A + ar*36 + aq2*4,     aBase + (size_t)ar*FDIM + _c32 + aq2*4); \
        cp16(_A + ar*36 + aq2*4 + 4, aBase + (size_t)ar*FDIM + _c32 + aq2*4 + 4); \
        _Pragma("unroll") \
        for (int j = 0; j < 8; j++) \
            cp16(_B + tid*36 + j*4, bBase + (size_t)tid*FDIM + _c32 + j*4); \
        CPCOMMIT; \
    } while (0)

    G1_LOAD(0, 0);
    G1_LOAD(1, 1);
    G1_LOAD(2, 2);

    float c[2][8][4];
    #pragma unroll
    for (int mt = 0; mt < 2; mt++)
        #pragma unroll
        for (int nt = 0; nt < 8; nt++)
            #pragma unroll
            for (int j = 0; j < 4; j++) c[mt][nt][j] = 0.f;

    int s = 0;
    #pragma unroll 1
    for (int ch = 0; ch < NCHUNK; ch++) {
        if (ch < NCHUNK-2)       CPWAIT(2);
        else if (ch == NCHUNK-2) CPWAIT(1);
        else                     CPWAIT(0);
        __syncthreads();
        const float* Asp = dsm + s*G1_STAGE;
        const float* Bsp = Asp + 64*36;
        #pragma unroll
        for (int k8 = 0; k8 < 4; k8++) {
            int kc = k8*8 + tg;
            uint32_t a[2][4];
            #pragma unroll
            for (int mt = 0; mt < 2; mt++) {
                const float* ap = Asp + (wm*32 + mt*16 + gid)*36 + kc;
                a[mt][0] = __float_as_uint(ap[0]);
                a[mt][1] = __float_as_uint(ap[8*36]);
                a[mt][2] = __float_as_uint(ap[4]);
                a[mt][3] = __float_as_uint(ap[8*36 + 4]);
            }
            #pragma unroll
            for (int nt = 0; nt < 8; nt++) {
                const float* bp = Bsp + (wn*64 + nt*8 + gid)*36 + kc;
                uint32_t b0 = __float_as_uint(bp[0]);
                uint32_t b1 = __float_as_uint(bp[4]);
                MMA_TF32(c[0][nt], a[0], b0, b1);
                MMA_TF32(c[1][nt], a[1], b0, b1);
            }
        }
        __syncthreads();
        if (ch + 3 < NCHUNK) G1_LOAD(ch+3, s);
        if (++s == 3) s = 0;
    }

    // epilogue: fragments -> g_part[slab][m][n]
    #pragma unroll
    for (int mt = 0; mt < 2; mt++) {
        int m = m0 + wm*32 + mt*16 + gid;
        float* rp = g_part + ((size_t)slab*MPAD + m)*HDIM + wn*64 + tg*2;
        #pragma unroll
        for (int nt = 0; nt < 8; nt++) {
            *(float2*)(rp + nt*8)            = make_float2(c[mt][nt][0], c[mt][nt][1]);
            *(float2*)(rp + nt*8 + 8*HDIM)   = make_float2(c[mt][nt][2], c[mt][nt][3]);
        }
    }
}

// ---------------- K5: GEMM2 + slab reduce + bias/leaky + keep + bb ----------------
__global__ void __launch_bounds__(256) gemm2_kernel(const float* __restrict__ W2,
        const float* __restrict__ b1, const float* __restrict__ b2,
        const float* __restrict__ orig_hw, float* __restrict__ out) {
    __shared__ __align__(16) float Ah[HDIM][16];     // [k][m]
    __shared__ __align__(16) float Bs[2][16][256];
    int m0 = blockIdx.x * 16;
    int tid = threadIdx.x;

    // A panel: reduce NSLAB slabs + b1 + leaky, store transposed
    #pragma unroll
    for (int q = 0; q < 4; q++) {
        int pos = q*256 + tid;
        int r = pos >> 6, f = pos & 63;
        const float* p0 = g_part + ((size_t)(m0 + r))*HDIM + f*4;
        float4 bv = *(const float4*)(b1 + f*4);
        float v0 = bv.x, v1 = bv.y, v2 = bv.z, v3 = bv.w;
        #pragma unroll
        for (int sl = 0; sl < NSLAB; sl++) {
            float4 sv = *(const float4*)(p0 + (size_t)sl*MPAD*HDIM);
            v0 += sv.x; v1 += sv.y; v2 += sv.z; v3 += sv.w;
        }
        v0 = v0 > 0.f ? v0 : 0.01f*v0;
        v1 = v1 > 0.f ? v1 : 0.01f*v1;
        v2 = v2 > 0.f ? v2 : 0.01f*v2;
        v3 = v3 > 0.f ? v3 : 0.01f*v3;
        Ah[f*4+0][r] = v0; Ah[f*4+1][r] = v1; Ah[f*4+2][r] = v2; Ah[f*4+3][r] = v3;
    }

    {
        int br = tid >> 6, bf = tid & 63;
        #pragma unroll
        for (int i = 0; i < 4; i++)
            cp16(&Bs[0][br + i*4][bf*4], W2 + (size_t)(br + i*4)*256 + bf*4);
        CPCOMMIT;
    }
    __syncthreads();

    int ty = tid >> 6, tx = tid & 63;
    ull acc[2][4];
    #pragma unroll
    for (int h = 0; h < 2; h++)
        #pragma unroll
        for (int j = 0; j < 4; j++) acc[h][j] = 0ull;

    #pragma unroll 1
    for (int kt = 0; kt < NKT2; kt++) {
        int st = kt & 1;
        if (kt + 1 < NKT2) {
            int br = tid >> 6, bf = tid & 63;
            #pragma unroll
            for (int i = 0; i < 4; i++)
                cp16(&Bs[st^1][br + i*4][bf*4], W2 + (size_t)((kt+1)*16 + br + i*4)*256 + bf*4);
            CPCOMMIT;
            asm volatile("cp.async.wait_group 1;" ::: "memory");
        } else {
            asm volatile("cp.async.wait_group 0;" ::: "memory");
        }
        __syncthreads();
        #pragma unroll
        for (int k = 0; k < 16; k++) {
            int kk = kt*16 + k;
            ull a0 = *(const ull*)&Ah[kk][ty*4];
            ull a1 = *(const ull*)&Ah[kk][ty*4 + 2];
            float4 bq = *(const float4*)&Bs[st][k][tx*4];
            ull bd[4];
            PACKDUP(bd[0], bq.x); PACKDUP(bd[1], bq.y); PACKDUP(bd[2], bq.z); PACKDUP(bd[3], bq.w);
            #pragma unroll
            for (int j = 0; j < 4; j++) { FFMA2(acc[0][j], a0, bd[j]); FFMA2(acc[1][j], a1, bd[j]); }
        }
        __syncthreads();
    }

    float4 bv2 = *(const float4*)(b2 + tx*4);
    float bb2[4] = { bv2.x, bv2.y, bv2.z, bv2.w };
    #pragma unroll
    for (int h = 0; h < 2; h++) {
        float lo[4], hi[4];
        #pragma unroll
        for (int j = 0; j < 4; j++) UNPACK2(lo[j], hi[j], acc[h][j]);
        int mr = m0 + ty*4 + 2*h;
        float kf0 = g_keep[mr], kf1 = g_keep[mr+1];
        float o0[4], o1[4];
        #pragma unroll
        for (int j = 0; j < 4; j++) {
            float v = lo[j] + bb2[j]; v = v > 0.f ? v : 0.01f*v; o0[j] = v * kf0;
            float u = hi[j] + bb2[j]; u = u > 0.f ? u : 0.01f*u; o1[j] = u * kf1;
        }
        *(float4*)(out + (size_t)mr*OUTC + 4 + tx*4)     = make_float4(o0[0],o0[1],o0[2],o0[3]);
        *(float4*)(out + (size_t)(mr+1)*OUTC + 4 + tx*4) = make_float4(o1[0],o1[1],o1[2],o1[3]);
    }

    if (tid < 16) {
        int m = m0 + tid;
        int bidx = m / MAXDET;
        const float* gb = g_boxes + (size_t)m*4;
        float oh = orig_hw[bidx*2 + 0], ow = orig_hw[bidx*2 + 1];
        float gain = fminf(640.f/oh, 640.f/ow);
        float padx = (640.f - ow*gain) * 0.5f;
        float pady = (640.f - oh*gain) * 0.5f;
        float kf = g_keep[m];
        float x1 = fminf(fmaxf((gb[0]-padx)/gain, 0.f), ow);
        float y1 = fminf(fmaxf((gb[1]-pady)/gain, 0.f), oh);
        float x2 = fminf(fmaxf((gb[2]-padx)/gain, 0.f), ow);
        float y2 = fminf(fmaxf((gb[3]-pady)/gain, 0.f), oh);
        *(float4*)(out + (size_t)m*OUTC) = make_float4(x1/ow*kf, y1/oh*kf, x2/ow*kf, y2/oh*kf);
    }
}

// ---------------- launch ----------------
extern "C" void kernel_launch(void* const* d_in, const int* in_sizes, int n_in,
                              void* d_out, int out_size) {
    const float* preds   = (const float*)d_in[0];
    const float* feat1   = (const float*)d_in[1];
    const float* feat2   = (const float*)d_in[2];
    const float* feat3   = (const float*)d_in[3];
    const float* feat4   = (const float*)d_in[4];
    const float* orig_hw = (const float*)d_in[5];
    const float* W1      = (const float*)d_in[6];
    const float* b1      = (const float*)d_in[7];
    const float* W2      = (const float*)d_in[8];
    const float* b2      = (const float*)d_in[9];
    float* out = (float*)d_out;
    (void)in_sizes; (void)n_in; (void)out_size;

    cudaFuncSetAttribute(gemm1_mma, cudaFuncAttributeMaxDynamicSharedMemorySize, G1_SMEM);

    prep_kernel<<<dim3(SCOREBLKS + TRTILES + W1TTILES, BATCH), 256>>>(preds, feat1, feat2, feat3, feat4, W1);
    select_kernel<<<BATCH, 1024>>>(preds);
    roi_kernel<<<dim3(MAXDET, BATCH), 480>>>();
    gemm1_mma<<<dim3(MPAD/64, NSLAB), 256, G1_SMEM>>>();
    gemm2_kernel<<<TOTDET/16, 256>>>(W2, b1, b2, orig_hw, out);
}

// round 15
// speedup vs baseline: 1.1653x; 1.0722x over previous
#include <cuda_runtime.h>
#include <cstdint>

#define BATCH 8
#define NANCH 25500
#define NCLS 80
#define PREDC 85
#define MAXDET 300
#define NBINS 1024
#define CMAX 1024
#define TOTDET (BATCH*MAXDET)   // 2400
#define FDIM 1920
#define HDIM 256
#define OUTC 260
#define MPAD 2432               // 19 * 128
#define NSLAB 6
#define KSLAB (FDIM/NSLAB)      // 320
#define NCHUNK (KSLAB/32)       // 10
#define NKT2 (HDIM/16)          // 16
#define SCOREBLKS 200
#define TRTILES 1536
#define W1TTILES 480            // (1920/32)*(256/32)
#define G1_STAGE 13824          // (128*36 + 256*36) floats
#define G1_SMEM (3*G1_STAGE*4)  // 165888 B

typedef unsigned long long ull;

// ---------------- scratch (static device globals; no allocation) ----------------
__device__ __align__(16) float g_conf[BATCH*NANCH];
__device__ int   g_cls [BATCH*NANCH];
__device__ int   g_hist[BATCH*NBINS];
__device__ __align__(16) float g_boxes[TOTDET*4];
__device__ float g_keep [TOTDET];
__device__ __align__(16) float g_t1[BATCH*6400*128];
__device__ __align__(16) float g_t2[BATCH*1600*256];
__device__ __align__(16) float g_t3[BATCH*400*512];
__device__ __align__(16) float g_t4[BATCH*100*1024];
__device__ __align__(16) float g_F [(size_t)MPAD*FDIM];           // rows >=2400 stay zero
__device__ __align__(16) float g_W1t[(size_t)HDIM*FDIM];          // W1^T [n][k]
__device__ __align__(16) float g_part[(size_t)NSLAB*MPAD*HDIM];   // [slab][m][n]

// ---------------- asm helpers ----------------
__device__ __forceinline__ void cp16(void* s, const void* g) {
    unsigned ss = (unsigned)__cvta_generic_to_shared(s);
    asm volatile("cp.async.cg.shared.global [%0], [%1], 16;" :: "r"(ss), "l"(g));
}
#define CPCOMMIT asm volatile("cp.async.commit_group;" ::: "memory")
#define CPWAIT(n) asm volatile("cp.async.wait_group %0;" :: "n"(n) : "memory")
#define FFMA2(d,a,b) asm volatile("fma.rn.f32x2 %0, %1, %2, %0;" : "+l"(d) : "l"(a), "l"(b))
#define PACKDUP(d,x) asm volatile("mov.b64 %0, {%1, %1};" : "=l"(d) : "f"(x))
#define UNPACK2(lo,hi,v) asm volatile("mov.b64 {%0, %1}, %2;" : "=f"(lo), "=f"(hi) : "l"(v))
// m16n8k8 tf32 mma, D = A*B + D
#define MMA_TF32(c, a, b0, b1) asm volatile( \
    "mma.sync.aligned.m16n8k8.row.col.f32.tf32.tf32.f32 " \
    "{%0,%1,%2,%3}, {%4,%5,%6,%7}, {%8,%9}, {%0,%1,%2,%3};" \
    : "+f"((c)[0]), "+f"((c)[1]), "+f"((c)[2]), "+f"((c)[3]) \
    : "r"((a)[0]), "r"((a)[1]), "r"((a)[2]), "r"((a)[3]), "r"(b0), "r"(b1))

// ---------------- K1: fused score + feature transpose + W1 transpose ----------------
__global__ void __launch_bounds__(256) prep_kernel(const float* __restrict__ preds,
        const float* __restrict__ f1, const float* __restrict__ f2,
        const float* __restrict__ f3, const float* __restrict__ f4,
        const float* __restrict__ W1) {
    __shared__ __align__(16) char smraw[128*PREDC*4 + NBINS*4];
    int blk = blockIdx.x, b = blockIdx.y;
    int t = threadIdx.x;

    if (blk < SCOREBLKS) {
        float* s = (float*)smraw;
        int* shist = (int*)(smraw + 128*PREDC*4);
        int n0 = blk * 128;
        int cnt = NANCH - n0; if (cnt > 128) cnt = 128;
        for (int i = t; i < NBINS; i += 256) shist[i] = 0;
        const float4* src = (const float4*)(preds + ((size_t)b*NANCH + n0) * PREDC);
        float4* s4 = (float4*)s;
        int tot4 = cnt * PREDC / 4;
        for (int i = t; i < tot4; i += 256) s4[i] = src[i];
        __syncthreads();
        if (t < cnt) {
            const float* a = s + t*PREDC;
            float obj = a[4];
            float best = a[5]*obj; int bc = 0;
            #pragma unroll 8
            for (int c = 1; c < NCLS; c++) {
                float v = a[5+c]*obj;
                if (v > best) { best = v; bc = c; }
            }
            float conf = best > 0.1f ? best : 0.f;
            g_conf[(size_t)b*NANCH + n0 + t] = conf;
            g_cls [(size_t)b*NANCH + n0 + t] = bc;
            if (conf > 0.1f) {
                int bin = (int)((conf - 0.1f) * (1024.f/0.9f));
                bin = min(max(bin, 0), NBINS-1);
                atomicAdd(&shist[bin], 1);
            }
        }
        __syncthreads();
        for (int i = t; i < NBINS; i += 256) {
            int v = shist[i];
            if (v) atomicAdd(&g_hist[b*NBINS + i], v);
        }
    } else {
        float (*tile)[33] = (float(*)[33])smraw;
        int tl = blk - SCOREBLKS;
        const float* src; float* dst; int C, HW, tp;
        if (tl < 800)        {             src = f1; dst = g_t1;  C = 128;  HW = 6400; tp = 200; }
        else if (tl < 1200)  { tl -= 800;  src = f2; dst = g_t2;  C = 256;  HW = 1600; tp = 50; }
        else if (tl < 1408)  { tl -= 1200; src = f3; dst = g_t3;  C = 512;  HW = 400;  tp = 13; }
        else if (tl < 1536)  { tl -= 1408; src = f4; dst = g_t4;  C = 1024; HW = 100;  tp = 4; }
        else                 { if (b > 0) return;
                               tl -= 1536; src = W1; dst = g_W1t; C = 1920; HW = 256;  tp = 8; b = 0; }
        if (C != 1920) { src += (size_t)b*C*HW; dst += (size_t)b*C*HW; }
        int p0 = (tl % tp) * 32, c0 = (tl / tp) * 32;
        int tx = t & 7, ty = t >> 3;
        {
            int p = p0 + tx*4;
            if (p < HW) {
                float4 v = *(const float4*)(src + (size_t)(c0 + ty)*HW + p);
                tile[tx*4+0][ty] = v.x; tile[tx*4+1][ty] = v.y;
                tile[tx*4+2][ty] = v.z; tile[tx*4+3][ty] = v.w;
            }
        }
        __syncthreads();
        {
            int p = p0 + ty;
            if (p < HW) {
                float4 v = make_float4(tile[ty][tx*4+0], tile[ty][tx*4+1],
                                       tile[ty][tx*4+2], tile[ty][tx*4+3]);
                *(float4*)(dst + (size_t)p*C + c0 + tx*4) = v;
            }
        }
    }
}

// ---------------- K2: fused threshold + compact + rank + NMS ----------------
__global__ void __launch_bounds__(1024) select_kernel(const float* __restrict__ preds) {
    __shared__ int s[NBINS];
    __shared__ int sthr, scnt;
    __shared__ float cc[CMAX];
    __shared__ int   ci[CMAX];
    __shared__ float tv[MAXDET];
    __shared__ int   tti[MAXDET];
    __shared__ float sx1[MAXDET], sy1[MAXDET], sx2[MAXDET], sy2[MAXDET], sar[MAXDET];
    __shared__ int   scls[MAXDET];
    __shared__ unsigned supm[MAXDET][10];
    __shared__ unsigned keepw[10];
    int b = blockIdx.x, t = threadIdx.x;

    s[t] = g_hist[b*NBINS + t];
    g_hist[b*NBINS + t] = 0;
    __syncthreads();
    for (int off = 1; off < NBINS; off <<= 1) {
        int v = (t + off < NBINS) ? s[t + off] : 0;
        __syncthreads();
        s[t] += v;
        __syncthreads();
    }
    if (s[t] >= MAXDET && (t == NBINS-1 || s[t+1] < MAXDET)) sthr = t;
    if (t == 0) { if (s[0] < MAXDET) sthr = 0; scnt = 0; }
    __syncthreads();
    int thr = sthr;

    for (int i = t; i < NANCH; i += 1024) {
        float conf = g_conf[(size_t)b*NANCH + i];
        if (conf > 0.1f) {
            int bin = (int)((conf - 0.1f) * (1024.f/0.9f));
            bin = min(max(bin, 0), NBINS-1);
            if (bin >= thr) {
                int p = atomicAdd(&scnt, 1);
                if (p < CMAX) { cc[p] = conf; ci[p] = i; }
            }
        }
    }
    __syncthreads();
    int M = min(scnt, CMAX);

    if (t < MAXDET) { tv[t] = 0.f; tti[t] = 0; }
    __syncthreads();
    for (int i = t; i < M; i += 1024) {
        float c = cc[i]; int id = ci[i];
        int r = 0;
        for (int j = 0; j < M; j++) {
            float cj = cc[j];
            r += (cj > c) || (cj == c && ci[j] < id);
        }
        if (r < MAXDET) { tv[r] = c; tti[r] = id; }
    }
    __syncthreads();

    bool act = t < MAXDET;
    bool valid = false;
    if (act) {
        int idx = tti[t];
        float conf = tv[t];
        const float* p = preds + ((size_t)b*NANCH + idx) * PREDC;
        float xc = p[0], yc = p[1], w = p[2], h = p[3];
        float x1 = xc - w*0.5f, y1 = yc - h*0.5f;
        float x2 = xc + w*0.5f, y2 = yc + h*0.5f;
        float* gb = g_boxes + ((size_t)b*MAXDET + t)*4;
        gb[0]=x1; gb[1]=y1; gb[2]=x2; gb[3]=y2;
        int cls = g_cls[(size_t)b*NANCH + idx];
        float off = (float)cls * 4096.0f;
        float vx1 = x1+off, vy1 = y1+off, vx2 = x2+off, vy2 = y2+off;
        sx1[t]=vx1; sy1[t]=vy1; sx2[t]=vx2; sy2[t]=vy2;
        sar[t] = (vx2-vx1)*(vy2-vy1);
        scls[t] = cls;
        valid = conf > 0.1f;
    }
    if (t < 320) {
        unsigned vb = __ballot_sync(0xffffffffu, valid);
        if ((t & 31) == 0) keepw[t >> 5] = vb;
    }
    __syncthreads();

    {
        int warp = t >> 5, lane = t & 31;
        for (int job = warp; job < MAXDET*10; job += 32) {
            int i = job / 10, word = job - i*10;
            int jb = word*32 + lane;
            int ic = scls[i];
            bool lact = (jb < MAXDET) && (jb > i);
            bool cm = lact && (scls[jb] == ic);
            unsigned anym = __ballot_sync(0xffffffffu, cm);
            bool sup = false;
            if (anym) {
                float ix1 = sx1[i], iy1 = sy1[i], ix2 = sx2[i], iy2 = sy2[i], iar = sar[i];
                if (cm) {
                    float lx = fmaxf(ix1, sx1[jb]), lyv = fmaxf(iy1, sy1[jb]);
                    float rx = fminf(ix2, sx2[jb]), ry  = fminf(iy2, sy2[jb]);
                    float iw = fmaxf(rx - lx, 0.f), ih = fmaxf(ry - lyv, 0.f);
                    float inter = iw * ih;
                    float iou = inter / (iar + sar[jb] - inter + 1e-7f);
                    sup = iou > 0.6f;
                }
            }
            unsigned m = __ballot_sync(0xffffffffu, sup);
            if (lane == 0) supm[i][word] = m;
        }
    }
    __syncthreads();

    if (t == 0) {
        unsigned kw[10];
        #pragma unroll
        for (int w = 0; w < 10; w++) kw[w] = keepw[w];
        #pragma unroll
        for (int w = 0; w < 10; w++) {
            unsigned bits = kw[w];
            while (bits) {
                int bit = __ffs(bits) - 1;
                bits &= bits - 1;
                int i = w*32 + bit;
                #pragma unroll
                for (int w2 = 0; w2 < 10; w2++) kw[w2] &= ~supm[i][w2];
                bits &= kw[w];
            }
        }
        #pragma unroll
        for (int w = 0; w < 10; w++) keepw[w] = kw[w];
    }
    __syncthreads();
    if (act) g_keep[b*MAXDET + t] = ((keepw[t>>5] >> (t&31)) & 1u) ? 1.f : 0.f;
}

// ---------------- K3: ROI align 1x1 ----------------
__global__ void __launch_bounds__(480) roi_kernel() {
    int det = blockIdx.x, b = blockIdx.y;
    int row = b*MAXDET + det;
    const float* gb = g_boxes + (size_t)row*4;
    float bx1 = gb[0], by1 = gb[1], bx2 = gb[2], by2 = gb[3];
    int q = threadIdx.x;
    const float* T; int C, H, W; float scale; int c0;
    if (q < 32)       { T = g_t1 + (size_t)b*6400*128; C = 128;  H = 80; W = 80; scale = 0.125f;    c0 = q*4; }
    else if (q < 96)  { T = g_t2 + (size_t)b*1600*256; C = 256;  H = 40; W = 40; scale = 0.0625f;   c0 = (q-32)*4; }
    else if (q < 224) { T = g_t3 + (size_t)b*400*512;  C = 512;  H = 20; W = 20; scale = 0.03125f;  c0 = (q-96)*4; }
    else              { T = g_t4 + (size_t)b*100*1024; C = 1024; H = 10; W = 10; scale = 0.015625f; c0 = (q-224)*4; }

    float x1 = bx1*scale, y1 = by1*scale, x2 = bx2*scale, y2 = by2*scale;
    float w = fmaxf(x2-x1, 1.f), h = fmaxf(y2-y1, 1.f);
    float xs[2] = { x1 + 0.5f*(w*0.5f), x1 + 1.5f*(w*0.5f) };
    float ys[2] = { y1 + 0.5f*(h*0.5f), y1 + 1.5f*(h*0.5f) };
    int pos[16]; float wt[16];
    int k = 0;
    #pragma unroll
    for (int py = 0; py < 2; py++) {
        #pragma unroll
        for (int px = 0; px < 2; px++) {
            float y = fminf(fmaxf(ys[py], 0.f), (float)(H-1));
            float x = fminf(fmaxf(xs[px], 0.f), (float)(W-1));
            float y0f = floorf(y), x0f = floorf(x);
            int y0 = (int)y0f, x0 = (int)x0f;
            int y1i = min(y0+1, H-1), x1i = min(x0+1, W-1);
            float ly = y - y0f, lx = x - x0f;
            pos[k] = (y0 *W + x0 )*C; wt[k] = (1.f-ly)*(1.f-lx)*0.25f; k++;
            pos[k] = (y0 *W + x1i)*C; wt[k] = (1.f-ly)*lx*0.25f;       k++;
            pos[k] = (y1i*W + x0 )*C; wt[k] = ly*(1.f-lx)*0.25f;       k++;
            pos[k] = (y1i*W + x1i)*C; wt[k] = ly*lx*0.25f;             k++;
        }
    }
    float4 acc = make_float4(0.f, 0.f, 0.f, 0.f);
    #pragma unroll
    for (int i = 0; i < 16; i++) {
        float4 v = *(const float4*)(T + pos[i] + c0);
        float wv = wt[i];
        acc.x += wv*v.x; acc.y += wv*v.y; acc.z += wv*v.z; acc.w += wv*v.w;
    }
    *(float4*)(g_F + (size_t)row*FDIM + q*4) = acc;
}

// ---------------- K4: GEMM1 mma.sync tf32 (114 blocks, BM=128, 512 thr, 3-stage) ----------------
__global__ void __launch_bounds__(512) gemm1_mma() {
    extern __shared__ __align__(16) float dsm[];
    // stage layout (floats): A[128*36] then B[256*36], 3 stages
    int tid = threadIdx.x;
    int m0 = blockIdx.x * 128;
    int slab = blockIdx.y;
    int kb = slab * KSLAB;
    int wid = tid >> 5, lane = tid & 31;
    int wm = wid >> 2, wn = wid & 3;        // warps: 4 (m) x 4 (n)
    int gid = lane >> 2, tg = lane & 3;

    const float* aBase = g_F + (size_t)m0*FDIM + kb;
    const float* bBase = g_W1t + kb;
    int ar = tid >> 2, aq2 = (tid & 3) * 2;   // A: row ar (0..127), float4 chunks aq2, aq2+1
    int br = tid >> 1, bq4 = (tid & 1) * 4;   // B: row br (0..255), float4 chunks bq4..bq4+3

    #define G1_LOAD(c, s) do { \
        int _c32 = (c)*32; \
        float* _A = dsm + (s)*G1_STAGE; float* _B = _A + 128*36; \
        cp16(_A + ar*36 + aq2*4,     aBase + (size_t)ar*FDIM + _c32 + aq2*4); \
        cp16(_A + ar*36 + aq2*4 + 4, aBase + (size_t)ar*FDIM + _c32 + aq2*4 + 4); \
        _Pragma("unroll") \
        for (int j = 0; j < 4; j++) \
            cp16(_B + br*36 + (bq4+j)*4, bBase + (size_t)br*FDIM + _c32 + (bq4+j)*4); \
        CPCOMMIT; \
    } while (0)

    G1_LOAD(0, 0);
    G1_LOAD(1, 1);
    G1_LOAD(2, 2);

    float c[2][8][4];
    #pragma unroll
    for (int mt = 0; mt < 2; mt++)
        #pragma unroll
        for (int nt = 0; nt < 8; nt++)
            #pragma unroll
            for (int j = 0; j < 4; j++) c[mt][nt][j] = 0.f;

    int s = 0;
    #pragma unroll 1
    for (int ch = 0; ch < NCHUNK; ch++) {
        if (ch < NCHUNK-2)       CPWAIT(2);
        else if (ch == NCHUNK-2) CPWAIT(1);
        else                     CPWAIT(0);
        __syncthreads();
        const float* Asp = dsm + s*G1_STAGE;
        const float* Bsp = Asp + 128*36;
        #pragma unroll
        for (int k8 = 0; k8 < 4; k8++) {
            int kc = k8*8 + tg;
            uint32_t a[2][4];
            #pragma unroll
            for (int mt = 0; mt < 2; mt++) {
                const float* ap = Asp + (wm*32 + mt*16 + gid)*36 + kc;
                a[mt][0] = __float_as_uint(ap[0]);
                a[mt][1] = __float_as_uint(ap[8*36]);
                a[mt][2] = __float_as_uint(ap[4]);
                a[mt][3] = __float_as_uint(ap[8*36 + 4]);
            }
            #pragma unroll
            for (int nt = 0; nt < 8; nt++) {
                const float* bp = Bsp + (wn*64 + nt*8 + gid)*36 + kc;
                uint32_t b0 = __float_as_uint(bp[0]);
                uint32_t b1 = __float_as_uint(bp[4]);
                MMA_TF32(c[0][nt], a[0], b0, b1);
                MMA_TF32(c[1][nt], a[1], b0, b1);
            }
        }
        __syncthreads();
        if (ch + 3 < NCHUNK) G1_LOAD(ch+3, s);
        if (++s == 3) s = 0;
    }

    // epilogue: fragments -> g_part[slab][m][n]
    #pragma unroll
    for (int mt = 0; mt < 2; mt++) {
        int m = m0 + wm*32 + mt*16 + gid;
        float* rp = g_part + ((size_t)slab*MPAD + m)*HDIM + wn*64 + tg*2;
        #pragma unroll
        for (int nt = 0; nt < 8; nt++) {
            *(float2*)(rp + nt*8)            = make_float2(c[mt][nt][0], c[mt][nt][1]);
            *(float2*)(rp + nt*8 + 8*HDIM)   = make_float2(c[mt][nt][2], c[mt][nt][3]);
        }
    }
}

// ---------------- K5: GEMM2 + slab reduce + bias/leaky + keep + bb ----------------
__global__ void __launch_bounds__(256) gemm2_kernel(const float* __restrict__ W2,
        const float* __restrict__ b1, const float* __restrict__ b2,
        const float* __restrict__ orig_hw, float* __restrict__ out) {
    __shared__ __align__(16) float Ah[HDIM][16];     // [k][m]
    __shared__ __align__(16) float Bs[2][16][256];
    int m0 = blockIdx.x * 16;
    int tid = threadIdx.x;

    // A panel: reduce NSLAB slabs + b1 + leaky, store transposed
    #pragma unroll
    for (int q = 0; q < 4; q++) {
        int pos = q*256 + tid;
        int r = pos >> 6, f = pos & 63;
        const float* p0 = g_part + ((size_t)(m0 + r))*HDIM + f*4;
        float4 bv = *(const float4*)(b1 + f*4);
        float v0 = bv.x, v1 = bv.y, v2 = bv.z, v3 = bv.w;
        #pragma unroll
        for (int sl = 0; sl < NSLAB; sl++) {
            float4 sv = *(const float4*)(p0 + (size_t)sl*MPAD*HDIM);
            v0 += sv.x; v1 += sv.y; v2 += sv.z; v3 += sv.w;
        }
        v0 = v0 > 0.f ? v0 : 0.01f*v0;
        v1 = v1 > 0.f ? v1 : 0.01f*v1;
        v2 = v2 > 0.f ? v2 : 0.01f*v2;
        v3 = v3 > 0.f ? v3 : 0.01f*v3;
        Ah[f*4+0][r] = v0; Ah[f*4+1][r] = v1; Ah[f*4+2][r] = v2; Ah[f*4+3][r] = v3;
    }

    {
        int br = tid >> 6, bf = tid & 63;
        #pragma unroll
        for (int i = 0; i < 4; i++)
            cp16(&Bs[0][br + i*4][bf*4], W2 + (size_t)(br + i*4)*256 + bf*4);
        CPCOMMIT;
    }
    __syncthreads();

    int ty = tid >> 6, tx = tid & 63;
    ull acc[2][4];
    #pragma unroll
    for (int h = 0; h < 2; h++)
        #pragma unroll
        for (int j = 0; j < 4; j++) acc[h][j] = 0ull;

    #pragma unroll 1
    for (int kt = 0; kt < NKT2; kt++) {
        int st = kt & 1;
        if (kt + 1 < NKT2) {
            int br = tid >> 6, bf = tid & 63;
            #pragma unroll
            for (int i = 0; i < 4; i++)
                cp16(&Bs[st^1][br + i*4][bf*4], W2 + (size_t)((kt+1)*16 + br + i*4)*256 + bf*4);
            CPCOMMIT;
            asm volatile("cp.async.wait_group 1;" ::: "memory");
        } else {
            asm volatile("cp.async.wait_group 0;" ::: "memory");
        }
        __syncthreads();
        #pragma unroll
        for (int k = 0; k < 16; k++) {
            int kk = kt*16 + k;
            ull a0 = *(const ull*)&Ah[kk][ty*4];
            ull a1 = *(const ull*)&Ah[kk][ty*4 + 2];
            float4 bq = *(const float4*)&Bs[st][k][tx*4];
            ull bd[4];
            PACKDUP(bd[0], bq.x); PACKDUP(bd[1], bq.y); PACKDUP(bd[2], bq.z); PACKDUP(bd[3], bq.w);
            #pragma unroll
            for (int j = 0; j < 4; j++) { FFMA2(acc[0][j], a0, bd[j]); FFMA2(acc[1][j], a1, bd[j]); }
        }
        __syncthreads();
    }

    float4 bv2 = *(const float4*)(b2 + tx*4);
    float bb2[4] = { bv2.x, bv2.y, bv2.z, bv2.w };
    #pragma unroll
    for (int h = 0; h < 2; h++) {
        float lo[4], hi[4];
        #pragma unroll
        for (int j = 0; j < 4; j++) UNPACK2(lo[j], hi[j], acc[h][j]);
        int mr = m0 + ty*4 + 2*h;
        float kf0 = g_keep[mr], kf1 = g_keep[mr+1];
        float o0[4], o1[4];
        #pragma unroll
        for (int j = 0; j < 4; j++) {
            float v = lo[j] + bb2[j]; v = v > 0.f ? v : 0.01f*v; o0[j] = v * kf0;
            float u = hi[j] + bb2[j]; u = u > 0.f ? u : 0.01f*u; o1[j] = u * kf1;
        }
        *(float4*)(out + (size_t)mr*OUTC + 4 + tx*4)     = make_float4(o0[0],o0[1],o0[2],o0[3]);
        *(float4*)(out + (size_t)(mr+1)*OUTC + 4 + tx*4) = make_float4(o1[0],o1[1],o1[2],o1[3]);
    }

    if (tid < 16) {
        int m = m0 + tid;
        int bidx = m / MAXDET;
        const float* gb = g_boxes + (size_t)m*4;
        float oh = orig_hw[bidx*2 + 0], ow = orig_hw[bidx*2 + 1];
        float gain = fminf(640.f/oh, 640.f/ow);
        float padx = (640.f - ow*gain) * 0.5f;
        float pady = (640.f - oh*gain) * 0.5f;
        float kf = g_keep[m];
        float x1 = fminf(fmaxf((gb[0]-padx)/gain, 0.f), ow);
        float y1 = fminf(fmaxf((gb[1]-pady)/gain, 0.f), oh);
        float x2 = fminf(fmaxf((gb[2]-padx)/gain, 0.f), ow);
        float y2 = fminf(fmaxf((gb[3]-pady)/gain, 0.f), oh);
        *(float4*)(out + (size_t)m*OUTC) = make_float4(x1/ow*kf, y1/oh*kf, x2/ow*kf, y2/oh*kf);
    }
}

// ---------------- launch ----------------
extern "C" void kernel_launch(void* const* d_in, const int* in_sizes, int n_in,
                              void* d_out, int out_size) {
    const float* preds   = (const float*)d_in[0];
    const float* feat1   = (const float*)d_in[1];
    const float* feat2   = (const float*)d_in[2];
    const float* feat3   = (const float*)d_in[3];
    const float* feat4   = (const float*)d_in[4];
    const float* orig_hw = (const float*)d_in[5];
    const float* W1      = (const float*)d_in[6];
    const float* b1      = (const float*)d_in[7];
    const float* W2      = (const float*)d_in[8];
    const float* b2      = (const float*)d_in[9];
    float* out = (float*)d_out;
    (void)in_sizes; (void)n_in; (void)out_size;

    cudaFuncSetAttribute(gemm1_mma, cudaFuncAttributeMaxDynamicSharedMemorySize, G1_SMEM);

    prep_kernel<<<dim3(SCOREBLKS + TRTILES + W1TTILES, BATCH), 256>>>(preds, feat1, feat2, feat3, feat4, W1);
    select_kernel<<<BATCH, 1024>>>(preds);
    roi_kernel<<<dim3(MAXDET, BATCH), 480>>>();
    gemm1_mma<<<dim3(MPAD/128, NSLAB), 512, G1_SMEM>>>();
    gemm2_kernel<<<TOTDET/16, 256>>>(W2, b1, b2, orig_hw, out);
}